// round 1
// baseline (speedup 1.0000x reference)
#include <cuda_runtime.h>
#include <math.h>

#define NN 100000
#define EE 1000000
#define NB1 98   // ceil(NN/1024)

// ---------------- scratch (static device globals; no allocation) -------------
__device__ float g_h128[(size_t)NN*128];   // per-layer features (N,2,64)
__device__ float g_x64[(size_t)NN*64];     // layer input (post-BN)
__device__ float g_buf64[(size_t)NN*64];   // aggregation output / MLP hidden
__device__ float g_as[NN*2];
__device__ float g_ad[NN*2];
__device__ int   g_deg[NN];
__device__ int   g_off[NN];                // inclusive scan of degrees
__device__ int   g_cursor[NN];
__device__ int   g_esrc[EE];               // src index sorted by dst
__device__ int   g_bsum[128];
__device__ int   g_bsumex[128];
__device__ float g_stats[128];             // sum[64], sumsq[64]

__device__ __forceinline__ float lrelu(float v){ return v > 0.f ? v : 0.2f*v; }

// ---------------- CSR build --------------------------------------------------
__global__ void k_zero_deg(){
  int i = blockIdx.x*blockDim.x + threadIdx.x;
  if (i < NN) g_deg[i] = 0;
}

__global__ void k_count(const int* __restrict__ ei){
  int e = blockIdx.x*blockDim.x + threadIdx.x;
  if (e < EE) atomicAdd(&g_deg[ei[EE + e]], 1);
}

__global__ void k_scan1(){
  __shared__ int s[256];
  int tid = threadIdx.x;
  int base = blockIdx.x*1024 + tid*4;
  int v[4]; int loc = 0;
  #pragma unroll
  for (int i = 0; i < 4; i++){ int idx = base + i; v[i] = (idx < NN) ? g_deg[idx] : 0; loc += v[i]; }
  s[tid] = loc; __syncthreads();
  #pragma unroll
  for (int d = 1; d < 256; d <<= 1){
    int t = (tid >= d) ? s[tid-d] : 0; __syncthreads();
    s[tid] += t; __syncthreads();
  }
  int run = (tid == 0) ? 0 : s[tid-1];
  #pragma unroll
  for (int i = 0; i < 4; i++){ run += v[i]; int idx = base + i; if (idx < NN) g_off[idx] = run; }
  if (tid == 255) g_bsum[blockIdx.x] = s[255];
}

__global__ void k_scan2(){
  __shared__ int s[128];
  int tid = threadIdx.x;
  int orig = (tid < NB1) ? g_bsum[tid] : 0;
  s[tid] = orig; __syncthreads();
  #pragma unroll
  for (int d = 1; d < 128; d <<= 1){
    int t = (tid >= d) ? s[tid-d] : 0; __syncthreads();
    s[tid] += t; __syncthreads();
  }
  g_bsumex[tid] = s[tid] - orig;   // exclusive prefix of block sums
}

__global__ void k_scan3(){
  int base = blockIdx.x*1024 + threadIdx.x*4;
  int add = g_bsumex[blockIdx.x];
  #pragma unroll
  for (int i = 0; i < 4; i++){ int idx = base + i; if (idx < NN) g_off[idx] += add; }
}

__global__ void k_cursor(){
  int i = blockIdx.x*blockDim.x + threadIdx.x;
  if (i < NN) g_cursor[i] = (i == 0) ? 0 : g_off[i-1];
}

__global__ void k_scatter(const int* __restrict__ ei){
  int e = blockIdx.x*blockDim.x + threadIdx.x;
  if (e < EE){
    int s = ei[e], d = ei[EE + e];
    int pos = atomicAdd(&g_cursor[d], 1);
    g_esrc[pos] = s;
  }
}

// ---------------- feature GEMM: h = X @ W  (DIN -> 128) ----------------------
template<int DIN, bool GX>
__global__ void __launch_bounds__(256) k_gemm(const float* __restrict__ Xin,
                                              const float* __restrict__ W){
  const float* X = GX ? (const float*)g_x64 : Xin;
  int j = threadIdx.x & 127;
  int g = threadIdx.x >> 7;
  float wreg[DIN];
  #pragma unroll
  for (int k = 0; k < DIN; k++) wreg[k] = W[k*128 + j];
  __shared__ __align__(16) float4 sx[2][DIN/4];
  for (int n0 = blockIdx.x*2; n0 < NN; n0 += gridDim.x*2){
    int n = n0 + g;
    if (n < NN && j < DIN/4)
      sx[g][j] = ((const float4*)(X + (size_t)n*DIN))[j];
    __syncthreads();
    if (n < NN){
      float acc = 0.f;
      #pragma unroll
      for (int k = 0; k < DIN/4; k++){
        float4 h4 = sx[g][k];
        acc += h4.x*wreg[4*k] + h4.y*wreg[4*k+1] + h4.z*wreg[4*k+2] + h4.w*wreg[4*k+3];
      }
      g_h128[(size_t)n*128 + j] = acc;
    }
    __syncthreads();
  }
}

// ---------------- attention prep: a_s, a_d per (node, head) ------------------
__global__ void __launch_bounds__(256) k_attprep(const float* __restrict__ aw,
                                                 const float* __restrict__ dw){
  int t = blockIdx.x*blockDim.x + threadIdx.x;
  int n = t >> 5, lane = t & 31;
  if (n >= NN) return;
  const float* hr = g_h128 + (size_t)n*128;
  float v0 = hr[lane], v1 = hr[lane+32], v2 = hr[lane+64], v3 = hr[lane+96];
  float ss0 = v0*aw[lane]    + v1*aw[lane+32];
  float ss1 = v2*aw[lane+64] + v3*aw[lane+96];
  float sd0 = v0*dw[lane]    + v1*dw[lane+32];
  float sd1 = v2*dw[lane+64] + v3*dw[lane+96];
  #pragma unroll
  for (int o = 16; o; o >>= 1){
    ss0 += __shfl_xor_sync(0xffffffffu, ss0, o);
    ss1 += __shfl_xor_sync(0xffffffffu, ss1, o);
    sd0 += __shfl_xor_sync(0xffffffffu, sd0, o);
    sd1 += __shfl_xor_sync(0xffffffffu, sd1, o);
  }
  if (lane == 0){
    g_as[2*n] = ss0; g_as[2*n+1] = ss1;
    g_ad[2*n] = sd0; g_ad[2*n+1] = sd1;
  }
}

// ---------------- GAT aggregation: one warp per destination node -------------
__global__ void __launch_bounds__(256) k_aggregate(const float* __restrict__ bias){
  int t = blockIdx.x*blockDim.x + threadIdx.x;
  int n = t >> 5, lane = t & 31;
  if (n >= NN) return;
  int start = n ? g_off[n-1] : 0;
  int end   = g_off[n];
  float ad0 = g_ad[2*n], ad1 = g_ad[2*n+1];
  float es0 = lrelu(g_as[2*n]   + ad0);
  float es1 = lrelu(g_as[2*n+1] + ad1);
  float m0 = es0, m1 = es1;
  for (int i = start + lane; i < end; i += 32){
    int s = g_esrc[i];
    m0 = fmaxf(m0, lrelu(g_as[2*s]   + ad0));
    m1 = fmaxf(m1, lrelu(g_as[2*s+1] + ad1));
  }
  #pragma unroll
  for (int o = 16; o; o >>= 1){
    m0 = fmaxf(m0, __shfl_xor_sync(0xffffffffu, m0, o));
    m1 = fmaxf(m1, __shfl_xor_sync(0xffffffffu, m1, o));
  }
  const float* hr = g_h128 + (size_t)n*128;
  float w0 = __expf(es0 - m0), w1 = __expf(es1 - m1);
  float den0 = w0, den1 = w1;
  float a0 = w0*hr[lane],    a1 = w0*hr[lane+32];
  float a2 = w1*hr[lane+64], a3 = w1*hr[lane+96];
  for (int i = start; i < end; i++){
    int s = g_esrc[i];
    float e0 = lrelu(g_as[2*s]   + ad0);
    float e1 = lrelu(g_as[2*s+1] + ad1);
    w0 = __expf(e0 - m0); w1 = __expf(e1 - m1);
    den0 += w0; den1 += w1;
    const float* hs = g_h128 + (size_t)s*128;
    a0 += w0*hs[lane];    a1 += w0*hs[lane+32];
    a2 += w1*hs[lane+64]; a3 += w1*hs[lane+96];
  }
  den0 += 1e-16f; den1 += 1e-16f;
  float r0 = 0.5f*(a0/den0 + a2/den1) + bias[lane];
  float r1 = 0.5f*(a1/den0 + a3/den1) + bias[lane+32];
  g_buf64[(size_t)n*64 + lane]      = r0;
  g_buf64[(size_t)n*64 + lane + 32] = r1;
}

// ---------------- batch norm -------------------------------------------------
__global__ void k_zero_stats(){ g_stats[threadIdx.x] = 0.f; }

__global__ void __launch_bounds__(256) k_bnstats(){
  int c = threadIdx.x & 63, g = threadIdx.x >> 6;
  float s = 0.f, q = 0.f;
  for (int n = blockIdx.x*4 + g; n < NN; n += gridDim.x*4){
    float v = g_buf64[(size_t)n*64 + c];
    s += v; q += v*v;
  }
  __shared__ float sh[256], shq[256];
  sh[threadIdx.x] = s; shq[threadIdx.x] = q; __syncthreads();
  if (g == 0){
    float ts = sh[c] + sh[c+64] + sh[c+128] + sh[c+192];
    float tq = shq[c] + shq[c+64] + shq[c+128] + shq[c+192];
    atomicAdd(&g_stats[c], ts);
    atomicAdd(&g_stats[64+c], tq);
  }
}

__global__ void __launch_bounds__(256) k_bnapply(const float* __restrict__ gam,
                                                 const float* __restrict__ bet){
  int idx = blockIdx.x*blockDim.x + threadIdx.x;
  if (idx >= NN*64) return;
  int c = idx & 63;
  const float inv = 1.f/(float)NN;
  float mean = g_stats[c]*inv;
  float var  = g_stats[64+c]*inv - mean*mean;
  float rstd = rsqrtf(var + 1e-5f);
  float y = (g_buf64[idx] - mean)*rstd*gam[c] + bet[c];
  g_x64[idx] = fmaxf(y, 0.f);
}

// ---------------- final MLP --------------------------------------------------
__global__ void __launch_bounds__(256) k_mlp1(const float* __restrict__ x,
                                              const float* __restrict__ W,
                                              const float* __restrict__ b){
  int j = threadIdx.x & 63, g = threadIdx.x >> 6;
  float wreg[69];
  #pragma unroll
  for (int k = 0; k < 69; k++) wreg[k] = W[k*64 + j];
  float bj = b[j];
  __shared__ __align__(16) float sh[4][72];
  for (int n0 = blockIdx.x*4; n0 < NN; n0 += gridDim.x*4){
    int n = n0 + g;
    if (n < NN){
      if (j < 16) ((float4*)sh[g])[j] = ((const float4*)(g_x64 + (size_t)n*64))[j];
      if (j >= 16 && j < 21) sh[g][48 + j] = x[(size_t)n*16 + (j - 7)];  // ctx = x[:,9:14]
    }
    __syncthreads();
    if (n < NN){
      float acc = bj;
      #pragma unroll
      for (int k = 0; k < 17; k++){
        float4 h4 = ((float4*)sh[g])[k];
        acc += h4.x*wreg[4*k] + h4.y*wreg[4*k+1] + h4.z*wreg[4*k+2] + h4.w*wreg[4*k+3];
      }
      acc += sh[g][68]*wreg[68];
      g_buf64[(size_t)n*64 + j] = fmaxf(acc, 0.f);
    }
    __syncthreads();
  }
}

__global__ void __launch_bounds__(256) k_mlp2(const float* __restrict__ W2,
                                              const float* __restrict__ b2,
                                              const float* __restrict__ pW,
                                              const float* __restrict__ pb,
                                              const float* __restrict__ vW,
                                              const float* __restrict__ vb,
                                              float* __restrict__ out){
  int j = threadIdx.x & 63, g = threadIdx.x >> 6, tid = threadIdx.x;
  float wreg[64];
  #pragma unroll
  for (int k = 0; k < 64; k++) wreg[k] = W2[k*64 + j];
  float b2j = b2[j], pwj = pW[j], vwj = vW[j];
  float pb0 = pb[0], vb0 = vb[0];
  __shared__ __align__(16) float st[4][64];
  __shared__ float rl[256], rv[256];
  for (int n0 = blockIdx.x*4; n0 < NN; n0 += gridDim.x*4){
    int n = n0 + g;
    if (n < NN && j < 16)
      ((float4*)st[g])[j] = ((const float4*)(g_buf64 + (size_t)n*64))[j];
    __syncthreads();
    float u = b2j;
    #pragma unroll
    for (int k = 0; k < 16; k++){
      float4 t4 = ((float4*)st[g])[k];
      u += t4.x*wreg[4*k] + t4.y*wreg[4*k+1] + t4.z*wreg[4*k+2] + t4.w*wreg[4*k+3];
    }
    rl[tid] = (n < NN) ? u*pwj : 0.f;
    rv[tid] = (n < NN) ? u*vwj : 0.f;
    __syncthreads();
    #pragma unroll
    for (int s = 32; s >= 1; s >>= 1){
      if (j < s){ rl[tid] += rl[tid+s]; rv[tid] += rv[tid+s]; }
      __syncthreads();
    }
    if (j == 0 && n < NN){
      out[n]      = rl[tid] + pb0;
      out[NN + n] = rv[tid] + vb0;
    }
    __syncthreads();
  }
}

// ---------------- launch -----------------------------------------------------
extern "C" void kernel_launch(void* const* d_in, const int* in_sizes, int n_in,
                              void* d_out, int out_size){
  const float* x   = (const float*)d_in[0];
  const int*   ei  = (const int*)  d_in[1];
  const float* W1  = (const float*)d_in[2];
  const float* as1 = (const float*)d_in[3];
  const float* ad1 = (const float*)d_in[4];
  const float* b1  = (const float*)d_in[5];
  const float* g1  = (const float*)d_in[6];
  const float* be1 = (const float*)d_in[7];
  const float* W2  = (const float*)d_in[8];
  const float* as2 = (const float*)d_in[9];
  const float* ad2 = (const float*)d_in[10];
  const float* b2  = (const float*)d_in[11];
  const float* g2  = (const float*)d_in[12];
  const float* be2 = (const float*)d_in[13];
  const float* W3  = (const float*)d_in[14];
  const float* as3 = (const float*)d_in[15];
  const float* ad3 = (const float*)d_in[16];
  const float* b3  = (const float*)d_in[17];
  const float* g3  = (const float*)d_in[18];
  const float* be3 = (const float*)d_in[19];
  const float* mW1 = (const float*)d_in[20];
  const float* mb1 = (const float*)d_in[21];
  const float* mW2 = (const float*)d_in[22];
  const float* mb2 = (const float*)d_in[23];
  const float* pW  = (const float*)d_in[24];
  const float* pb  = (const float*)d_in[25];
  const float* vW  = (const float*)d_in[26];
  const float* vb  = (const float*)d_in[27];
  float* out = (float*)d_out;

  const int TB = 256;
  const int gN   = (NN + TB - 1)/TB;
  const int gE   = (EE + TB - 1)/TB;
  const int gWarp = (NN*32 + TB - 1)/TB;   // warp-per-node kernels
  const int gElem = (NN*64 + TB - 1)/TB;
  const int gGemm = 1184;                  // 8 * 148 SMs

  // CSR build (per-launch; deterministic work)
  k_zero_deg<<<gN, TB>>>();
  k_count<<<gE, TB>>>(ei);
  k_scan1<<<NB1, TB>>>();
  k_scan2<<<1, 128>>>();
  k_scan3<<<NB1, TB>>>();
  k_cursor<<<gN, TB>>>();
  k_scatter<<<gE, TB>>>(ei);

  // layer 1
  k_gemm<16,false><<<gGemm, TB>>>(x, W1);
  k_attprep<<<gWarp, TB>>>(as1, ad1);
  k_aggregate<<<gWarp, TB>>>(b1);
  k_zero_stats<<<1, 128>>>();
  k_bnstats<<<128, TB>>>();
  k_bnapply<<<gElem, TB>>>(g1, be1);

  // layer 2
  k_gemm<64,true><<<gGemm, TB>>>(nullptr, W2);
  k_attprep<<<gWarp, TB>>>(as2, ad2);
  k_aggregate<<<gWarp, TB>>>(b2);
  k_zero_stats<<<1, 128>>>();
  k_bnstats<<<128, TB>>>();
  k_bnapply<<<gElem, TB>>>(g2, be2);

  // layer 3
  k_gemm<64,true><<<gGemm, TB>>>(nullptr, W3);
  k_attprep<<<gWarp, TB>>>(as3, ad3);
  k_aggregate<<<gWarp, TB>>>(b3);
  k_zero_stats<<<1, 128>>>();
  k_bnstats<<<128, TB>>>();
  k_bnapply<<<gElem, TB>>>(g3, be3);

  // MLP + heads
  k_mlp1<<<gGemm, TB>>>(x, mW1, mb1);
  k_mlp2<<<gGemm, TB>>>(mW2, mb2, pW, pb, vW, vb, out);
}

// round 2
// speedup vs baseline: 1.0608x; 1.0608x over previous
#include <cuda_runtime.h>
#include <math.h>

#define NN 100000
#define EE 1000000
#define NB1 98   // ceil(NN/1024)

// ---------------- scratch (static device globals; no allocation) -------------
__device__ float g_h128[(size_t)NN*128];   // per-layer features (N,2,64)
__device__ float g_buf64[(size_t)NN*64];   // aggregation output / MLP hidden
__device__ float g_as[NN*2];
__device__ float g_ad[NN*2];
__device__ int   g_deg[NN];
__device__ int   g_off[NN];                // inclusive scan of degrees
__device__ int   g_cursor[NN];
__device__ int   g_esrc[EE];               // src index sorted by dst
__device__ int   g_bsum[128];
__device__ int   g_bsumex[128];
__device__ float g_part[128*128];          // per-block BN partials: [block][sum64|sumsq64]
__device__ float g_bnscale[64];
__device__ float g_bnshift[64];

__device__ __forceinline__ float lrelu(float v){ return v > 0.f ? v : 0.2f*v; }

// ---------------- CSR build --------------------------------------------------
__global__ void k_zero_deg(){
  int i = blockIdx.x*blockDim.x + threadIdx.x;
  if (i < NN) g_deg[i] = 0;
}

__global__ void k_count(const int* __restrict__ ei){
  int e = blockIdx.x*blockDim.x + threadIdx.x;
  if (e < EE) atomicAdd(&g_deg[ei[EE + e]], 1);
}

__global__ void k_scan1(){
  __shared__ int s[256];
  int tid = threadIdx.x;
  int base = blockIdx.x*1024 + tid*4;
  int v[4]; int loc = 0;
  #pragma unroll
  for (int i = 0; i < 4; i++){ int idx = base + i; v[i] = (idx < NN) ? g_deg[idx] : 0; loc += v[i]; }
  s[tid] = loc; __syncthreads();
  #pragma unroll
  for (int d = 1; d < 256; d <<= 1){
    int t = (tid >= d) ? s[tid-d] : 0; __syncthreads();
    s[tid] += t; __syncthreads();
  }
  int run = (tid == 0) ? 0 : s[tid-1];
  #pragma unroll
  for (int i = 0; i < 4; i++){ run += v[i]; int idx = base + i; if (idx < NN) g_off[idx] = run; }
  if (tid == 255) g_bsum[blockIdx.x] = s[255];
}

__global__ void k_scan2(){
  __shared__ int s[128];
  int tid = threadIdx.x;
  int orig = (tid < NB1) ? g_bsum[tid] : 0;
  s[tid] = orig; __syncthreads();
  #pragma unroll
  for (int d = 1; d < 128; d <<= 1){
    int t = (tid >= d) ? s[tid-d] : 0; __syncthreads();
    s[tid] += t; __syncthreads();
  }
  g_bsumex[tid] = s[tid] - orig;   // exclusive prefix of block sums
}

__global__ void k_scan3(){
  int base = blockIdx.x*1024 + threadIdx.x*4;
  int add = g_bsumex[blockIdx.x];
  #pragma unroll
  for (int i = 0; i < 4; i++){ int idx = base + i; if (idx < NN) g_off[idx] += add; }
}

__global__ void k_cursor(){
  int i = blockIdx.x*blockDim.x + threadIdx.x;
  if (i < NN) g_cursor[i] = (i == 0) ? 0 : g_off[i-1];
}

__global__ void k_scatter(const int* __restrict__ ei){
  int e = blockIdx.x*blockDim.x + threadIdx.x;
  if (e < EE){
    int s = ei[e], d = ei[EE + e];
    int pos = atomicAdd(&g_cursor[d], 1);
    g_esrc[pos] = s;
  }
}

// ---------------- feature GEMM: h = X @ W  (DIN -> 128) ----------------------
// BN=true: read g_buf64 and apply per-channel scale/shift + relu at load time.
template<int DIN, bool BN>
__global__ void __launch_bounds__(256) k_gemm(const float* __restrict__ Xin,
                                              const float* __restrict__ W){
  const float* X = BN ? (const float*)g_buf64 : Xin;
  int j = threadIdx.x & 127;
  int g = threadIdx.x >> 7;
  float wreg[DIN];
  #pragma unroll
  for (int k = 0; k < DIN; k++) wreg[k] = W[k*128 + j];
  float4 sc4, sh4;
  if (BN && j < DIN/4){
    sc4 = ((const float4*)g_bnscale)[j];
    sh4 = ((const float4*)g_bnshift)[j];
  }
  __shared__ __align__(16) float4 sx[2][DIN/4];
  for (int n0 = blockIdx.x*2; n0 < NN; n0 += gridDim.x*2){
    int n = n0 + g;
    if (n < NN && j < DIN/4){
      float4 v = ((const float4*)(X + (size_t)n*DIN))[j];
      if (BN){
        v.x = fmaxf(v.x*sc4.x + sh4.x, 0.f);
        v.y = fmaxf(v.y*sc4.y + sh4.y, 0.f);
        v.z = fmaxf(v.z*sc4.z + sh4.z, 0.f);
        v.w = fmaxf(v.w*sc4.w + sh4.w, 0.f);
      }
      sx[g][j] = v;
    }
    __syncthreads();
    if (n < NN){
      float acc0 = 0.f, acc1 = 0.f, acc2 = 0.f, acc3 = 0.f;
      #pragma unroll
      for (int k = 0; k < DIN/4; k++){
        float4 h4 = sx[g][k];
        acc0 += h4.x*wreg[4*k];   acc1 += h4.y*wreg[4*k+1];
        acc2 += h4.z*wreg[4*k+2]; acc3 += h4.w*wreg[4*k+3];
      }
      g_h128[(size_t)n*128 + j] = (acc0+acc1)+(acc2+acc3);
    }
    __syncthreads();
  }
}

// ---------------- attention prep: a_s, a_d per (node, head) ------------------
__global__ void __launch_bounds__(256) k_attprep(const float* __restrict__ aw,
                                                 const float* __restrict__ dw){
  int t = blockIdx.x*blockDim.x + threadIdx.x;
  int n = t >> 5, lane = t & 31;
  if (n >= NN) return;
  const float* hr = g_h128 + (size_t)n*128;
  float v0 = hr[lane], v1 = hr[lane+32], v2 = hr[lane+64], v3 = hr[lane+96];
  float ss0 = v0*aw[lane]    + v1*aw[lane+32];
  float ss1 = v2*aw[lane+64] + v3*aw[lane+96];
  float sd0 = v0*dw[lane]    + v1*dw[lane+32];
  float sd1 = v2*dw[lane+64] + v3*dw[lane+96];
  #pragma unroll
  for (int o = 16; o; o >>= 1){
    ss0 += __shfl_xor_sync(0xffffffffu, ss0, o);
    ss1 += __shfl_xor_sync(0xffffffffu, ss1, o);
    sd0 += __shfl_xor_sync(0xffffffffu, sd0, o);
    sd1 += __shfl_xor_sync(0xffffffffu, sd1, o);
  }
  if (lane == 0){
    g_as[2*n] = ss0; g_as[2*n+1] = ss1;
    g_ad[2*n] = sd0; g_ad[2*n+1] = sd1;
  }
}

// ---------------- GAT aggregation: one warp per destination node -------------
// Lane-parallel edge phase (coalesced esrc load, one exp per edge/head),
// then register-shuffle broadcast for the weighted feature accumulation so
// all h[src] loads are independent (MLP-deep, bandwidth-bound).
__global__ void __launch_bounds__(256) k_aggregate(const float* __restrict__ bias){
  int t = blockIdx.x*blockDim.x + threadIdx.x;
  int n = t >> 5, lane = t & 31;
  if (n >= NN) return;
  int start = n ? g_off[n-1] : 0;
  int end   = g_off[n];
  int len   = end - start;
  float ad0 = g_ad[2*n], ad1 = g_ad[2*n+1];
  float es0 = lrelu(g_as[2*n]   + ad0);   // self loop
  float es1 = lrelu(g_as[2*n+1] + ad1);
  const float* hr = g_h128 + (size_t)n*128;

  float a0, a1, a2, a3, den0, den1;

  if (len <= 32){
    int s = 0; float e0 = -1e30f, e1 = -1e30f;
    if (lane < len){
      s  = g_esrc[start + lane];
      e0 = lrelu(g_as[2*s]   + ad0);
      e1 = lrelu(g_as[2*s+1] + ad1);
    }
    float m0 = fmaxf(e0, es0), m1 = fmaxf(e1, es1);
    #pragma unroll
    for (int o = 16; o; o >>= 1){
      m0 = fmaxf(m0, __shfl_xor_sync(0xffffffffu, m0, o));
      m1 = fmaxf(m1, __shfl_xor_sync(0xffffffffu, m1, o));
    }
    float w0 = (lane < len) ? __expf(e0 - m0) : 0.f;
    float w1 = (lane < len) ? __expf(e1 - m1) : 0.f;
    float d0 = w0, d1 = w1;
    #pragma unroll
    for (int o = 16; o; o >>= 1){
      d0 += __shfl_xor_sync(0xffffffffu, d0, o);
      d1 += __shfl_xor_sync(0xffffffffu, d1, o);
    }
    float ws0 = __expf(es0 - m0), ws1 = __expf(es1 - m1);
    den0 = d0 + ws0 + 1e-16f;
    den1 = d1 + ws1 + 1e-16f;
    a0 = ws0*hr[lane];    a1 = ws0*hr[lane+32];
    a2 = ws1*hr[lane+64]; a3 = ws1*hr[lane+96];
    #pragma unroll 4
    for (int k = 0; k < len; k++){
      int   sk  = __shfl_sync(0xffffffffu, s,  k);
      float wk0 = __shfl_sync(0xffffffffu, w0, k);
      float wk1 = __shfl_sync(0xffffffffu, w1, k);
      const float* hs = g_h128 + (size_t)sk*128;
      a0 += wk0*hs[lane];    a1 += wk0*hs[lane+32];
      a2 += wk1*hs[lane+64]; a3 += wk1*hs[lane+96];
    }
  } else {
    // rare high-degree path: two passes, chunked
    float m0 = es0, m1 = es1;
    for (int i = start + lane; i < end; i += 32){
      int s = g_esrc[i];
      m0 = fmaxf(m0, lrelu(g_as[2*s]   + ad0));
      m1 = fmaxf(m1, lrelu(g_as[2*s+1] + ad1));
    }
    #pragma unroll
    for (int o = 16; o; o >>= 1){
      m0 = fmaxf(m0, __shfl_xor_sync(0xffffffffu, m0, o));
      m1 = fmaxf(m1, __shfl_xor_sync(0xffffffffu, m1, o));
    }
    float ws0 = __expf(es0 - m0), ws1 = __expf(es1 - m1);
    a0 = ws0*hr[lane];    a1 = ws0*hr[lane+32];
    a2 = ws1*hr[lane+64]; a3 = ws1*hr[lane+96];
    float d0 = 0.f, d1 = 0.f;
    for (int base = start; base < end; base += 32){
      int cnt = min(32, end - base);
      int s = 0; float w0 = 0.f, w1 = 0.f;
      if (lane < cnt){
        s  = g_esrc[base + lane];
        w0 = __expf(lrelu(g_as[2*s]   + ad0) - m0);
        w1 = __expf(lrelu(g_as[2*s+1] + ad1) - m1);
      }
      d0 += w0; d1 += w1;
      for (int k = 0; k < cnt; k++){
        int   sk  = __shfl_sync(0xffffffffu, s,  k);
        float wk0 = __shfl_sync(0xffffffffu, w0, k);
        float wk1 = __shfl_sync(0xffffffffu, w1, k);
        const float* hs = g_h128 + (size_t)sk*128;
        a0 += wk0*hs[lane];    a1 += wk0*hs[lane+32];
        a2 += wk1*hs[lane+64]; a3 += wk1*hs[lane+96];
      }
    }
    #pragma unroll
    for (int o = 16; o; o >>= 1){
      d0 += __shfl_xor_sync(0xffffffffu, d0, o);
      d1 += __shfl_xor_sync(0xffffffffu, d1, o);
    }
    den0 = d0 + ws0 + 1e-16f;
    den1 = d1 + ws1 + 1e-16f;
  }

  float r0 = 0.5f*(a0/den0 + a2/den1) + bias[lane];
  float r1 = 0.5f*(a1/den0 + a3/den1) + bias[lane+32];
  g_buf64[(size_t)n*64 + lane]      = r0;
  g_buf64[(size_t)n*64 + lane + 32] = r1;
}

// ---------------- batch norm stats (partials, no atomics) --------------------
__global__ void __launch_bounds__(256) k_bnstats(){
  int c = threadIdx.x & 63, g = threadIdx.x >> 6;
  float s = 0.f, q = 0.f;
  for (int n = blockIdx.x*4 + g; n < NN; n += gridDim.x*4){
    float v = g_buf64[(size_t)n*64 + c];
    s += v; q += v*v;
  }
  __shared__ float sh[256], shq[256];
  sh[threadIdx.x] = s; shq[threadIdx.x] = q; __syncthreads();
  if (g == 0){
    float ts = sh[c] + sh[c+64] + sh[c+128] + sh[c+192];
    float tq = shq[c] + shq[c+64] + shq[c+128] + shq[c+192];
    g_part[blockIdx.x*128 + c]      = ts;
    g_part[blockIdx.x*128 + 64 + c] = tq;
  }
}

// reduce partials -> per-channel scale/shift for fused BN+relu in next GEMM
__global__ void k_bnfinal(const float* __restrict__ gam,
                          const float* __restrict__ bet){
  int c = threadIdx.x;   // 64 threads
  float s = 0.f, q = 0.f;
  #pragma unroll 8
  for (int b = 0; b < 128; b++){
    s += g_part[b*128 + c];
    q += g_part[b*128 + 64 + c];
  }
  const float inv = 1.f/(float)NN;
  float mean = s*inv;
  float var  = q*inv - mean*mean;
  float rstd = rsqrtf(var + 1e-5f);
  float sc = rstd*gam[c];
  g_bnscale[c] = sc;
  g_bnshift[c] = bet[c] - mean*sc;
}

// ---------------- final MLP (applies BN3 at load) ----------------------------
__global__ void __launch_bounds__(256) k_mlp1(const float* __restrict__ x,
                                              const float* __restrict__ W,
                                              const float* __restrict__ b){
  int j = threadIdx.x & 63, g = threadIdx.x >> 6;
  float wreg[69];
  #pragma unroll
  for (int k = 0; k < 69; k++) wreg[k] = W[k*64 + j];
  float bj = b[j];
  float4 sc4, sh4;
  if (j < 16){
    sc4 = ((const float4*)g_bnscale)[j];
    sh4 = ((const float4*)g_bnshift)[j];
  }
  __shared__ __align__(16) float sh[4][72];
  for (int n0 = blockIdx.x*4; n0 < NN; n0 += gridDim.x*4){
    int n = n0 + g;
    if (n < NN){
      if (j < 16){
        float4 v = ((const float4*)(g_buf64 + (size_t)n*64))[j];
        v.x = fmaxf(v.x*sc4.x + sh4.x, 0.f);
        v.y = fmaxf(v.y*sc4.y + sh4.y, 0.f);
        v.z = fmaxf(v.z*sc4.z + sh4.z, 0.f);
        v.w = fmaxf(v.w*sc4.w + sh4.w, 0.f);
        ((float4*)sh[g])[j] = v;
      }
      if (j >= 16 && j < 21) sh[g][48 + j] = x[(size_t)n*16 + (j - 7)];  // ctx = x[:,9:14]
    }
    __syncthreads();
    if (n < NN){
      float acc = bj;
      #pragma unroll
      for (int k = 0; k < 17; k++){
        float4 h4 = ((float4*)sh[g])[k];
        acc += h4.x*wreg[4*k] + h4.y*wreg[4*k+1] + h4.z*wreg[4*k+2] + h4.w*wreg[4*k+3];
      }
      acc += sh[g][68]*wreg[68];
      g_h128[(size_t)n*64 + j] = fmaxf(acc, 0.f);   // reuse g_h128 as hidden buffer
    }
    __syncthreads();
  }
}

__global__ void __launch_bounds__(256) k_mlp2(const float* __restrict__ W2,
                                              const float* __restrict__ b2,
                                              const float* __restrict__ pW,
                                              const float* __restrict__ pb,
                                              const float* __restrict__ vW,
                                              const float* __restrict__ vb,
                                              float* __restrict__ out){
  int j = threadIdx.x & 63, g = threadIdx.x >> 6, tid = threadIdx.x;
  float wreg[64];
  #pragma unroll
  for (int k = 0; k < 64; k++) wreg[k] = W2[k*64 + j];
  float b2j = b2[j], pwj = pW[j], vwj = vW[j];
  float pb0 = pb[0], vb0 = vb[0];
  __shared__ __align__(16) float st[4][64];
  __shared__ float rl[256], rv[256];
  for (int n0 = blockIdx.x*4; n0 < NN; n0 += gridDim.x*4){
    int n = n0 + g;
    if (n < NN && j < 16)
      ((float4*)st[g])[j] = ((const float4*)(g_h128 + (size_t)n*64))[j];
    __syncthreads();
    float u = b2j;
    #pragma unroll
    for (int k = 0; k < 16; k++){
      float4 t4 = ((float4*)st[g])[k];
      u += t4.x*wreg[4*k] + t4.y*wreg[4*k+1] + t4.z*wreg[4*k+2] + t4.w*wreg[4*k+3];
    }
    rl[tid] = (n < NN) ? u*pwj : 0.f;
    rv[tid] = (n < NN) ? u*vwj : 0.f;
    __syncthreads();
    #pragma unroll
    for (int s = 32; s >= 1; s >>= 1){
      if (j < s){ rl[tid] += rl[tid+s]; rv[tid] += rv[tid+s]; }
      __syncthreads();
    }
    if (j == 0 && n < NN){
      out[n]      = rl[tid] + pb0;
      out[NN + n] = rv[tid] + vb0;
    }
    __syncthreads();
  }
}

// ---------------- launch -----------------------------------------------------
extern "C" void kernel_launch(void* const* d_in, const int* in_sizes, int n_in,
                              void* d_out, int out_size){
  const float* x   = (const float*)d_in[0];
  const int*   ei  = (const int*)  d_in[1];
  const float* W1  = (const float*)d_in[2];
  const float* as1 = (const float*)d_in[3];
  const float* ad1 = (const float*)d_in[4];
  const float* b1  = (const float*)d_in[5];
  const float* g1  = (const float*)d_in[6];
  const float* be1 = (const float*)d_in[7];
  const float* W2  = (const float*)d_in[8];
  const float* as2 = (const float*)d_in[9];
  const float* ad2 = (const float*)d_in[10];
  const float* b2  = (const float*)d_in[11];
  const float* g2  = (const float*)d_in[12];
  const float* be2 = (const float*)d_in[13];
  const float* W3  = (const float*)d_in[14];
  const float* as3 = (const float*)d_in[15];
  const float* ad3 = (const float*)d_in[16];
  const float* b3  = (const float*)d_in[17];
  const float* g3  = (const float*)d_in[18];
  const float* be3 = (const float*)d_in[19];
  const float* mW1 = (const float*)d_in[20];
  const float* mb1 = (const float*)d_in[21];
  const float* mW2 = (const float*)d_in[22];
  const float* mb2 = (const float*)d_in[23];
  const float* pW  = (const float*)d_in[24];
  const float* pb  = (const float*)d_in[25];
  const float* vW  = (const float*)d_in[26];
  const float* vb  = (const float*)d_in[27];
  float* out = (float*)d_out;

  const int TB = 256;
  const int gN    = (NN + TB - 1)/TB;
  const int gE    = (EE + TB - 1)/TB;
  const int gWarp = (NN*32 + TB - 1)/TB;   // warp-per-node kernels
  const int gGemm = 1184;                  // 8 * 148 SMs

  // CSR build (per-launch; deterministic work)
  k_zero_deg<<<gN, TB>>>();
  k_count<<<gE, TB>>>(ei);
  k_scan1<<<NB1, TB>>>();
  k_scan2<<<1, 128>>>();
  k_scan3<<<NB1, TB>>>();
  k_cursor<<<gN, TB>>>();
  k_scatter<<<gE, TB>>>(ei);

  // layer 1
  k_gemm<16,false><<<gGemm, TB>>>(x, W1);
  k_attprep<<<gWarp, TB>>>(as1, ad1);
  k_aggregate<<<gWarp, TB>>>(b1);
  k_bnstats<<<128, TB>>>();
  k_bnfinal<<<1, 64>>>(g1, be1);

  // layer 2
  k_gemm<64,true><<<gGemm, TB>>>(nullptr, W2);
  k_attprep<<<gWarp, TB>>>(as2, ad2);
  k_aggregate<<<gWarp, TB>>>(b2);
  k_bnstats<<<128, TB>>>();
  k_bnfinal<<<1, 64>>>(g2, be2);

  // layer 3
  k_gemm<64,true><<<gGemm, TB>>>(nullptr, W3);
  k_attprep<<<gWarp, TB>>>(as3, ad3);
  k_aggregate<<<gWarp, TB>>>(b3);
  k_bnstats<<<128, TB>>>();
  k_bnfinal<<<1, 64>>>(g3, be3);

  // MLP + heads
  k_mlp1<<<gGemm, TB>>>(x, mW1, mb1);
  k_mlp2<<<gGemm, TB>>>(mW2, mb2, pW, pb, vW, vb, out);
}